// round 9
// baseline (speedup 1.0000x reference)
#include <cuda_runtime.h>

#define BB 2
#define SS 2048
#define DD 768
#define HH 12
#define DKK 64
#define MM (BB*SS)   // 4096

// ---------------- scratch (static device globals) ---------------------------
__device__ float g_q[MM * DD];
__device__ float g_k[MM * DD];
__device__ float g_v[MM * DD];
__device__ float g_o[MM * DD];
__device__ float g_rz[BB * HH * SS];      // 1 / sum_i exp(s[b,h,j,i])
__device__ float g_in[3 * MM * DD];       // tf32-rounded query/key/value
__device__ float g_w [4 * DD * DD];       // tf32-rounded Wq/Wk/Wv/Wo

// ---------------- helpers ----------------------------------------------------
__device__ __forceinline__ void cpa16(void* s, const void* g) {
    unsigned sa = (unsigned)__cvta_generic_to_shared(s);
    asm volatile("cp.async.ca.shared.global [%0], [%1], 16;\n" :: "r"(sa), "l"(g));
}
__device__ __forceinline__ void cp_commit() { asm volatile("cp.async.commit_group;\n"); }
template<int N> __device__ __forceinline__ void cp_wait() {
    asm volatile("cp.async.wait_group %0;\n" :: "n"(N));
}
__device__ __forceinline__ unsigned f2tf(float f) {
    unsigned u;
    asm("cvt.rna.tf32.f32 %0, %1;" : "=r"(u) : "f"(f));
    return u;
}
__device__ __forceinline__ float rndtf(float f) { return __uint_as_float(f2tf(f)); }

// D += A(16x8) * B(8x8), tf32, f32 accum
__device__ __forceinline__ void mma8(float c[4], const unsigned a[4], const unsigned b[2]) {
    asm volatile(
        "mma.sync.aligned.m16n8k8.row.col.f32.tf32.tf32.f32 "
        "{%0,%1,%2,%3}, {%4,%5,%6,%7}, {%8,%9}, {%0,%1,%2,%3};"
        : "+f"(c[0]), "+f"(c[1]), "+f"(c[2]), "+f"(c[3])
        : "r"(a[0]), "r"(a[1]), "r"(a[2]), "r"(a[3]), "r"(b[0]), "r"(b[1]));
}

// ============================================================================
// tf32 pre-rounding prepass (elementwise, float4)
// ============================================================================
__global__ void round_inputs_k(const float* __restrict__ q,
                               const float* __restrict__ k,
                               const float* __restrict__ v,
                               float* __restrict__ dst)
{
    const float* src = (blockIdx.y == 0) ? q : (blockIdx.y == 1) ? k : v;
    float* d = dst + (size_t)blockIdx.y * MM * DD;
    int idx = (blockIdx.x * 256 + threadIdx.x) << 2;
    if (idx < MM * DD) {
        float4 x = *(const float4*)(src + idx);
        x.x = rndtf(x.x); x.y = rndtf(x.y); x.z = rndtf(x.z); x.w = rndtf(x.w);
        *(float4*)(d + idx) = x;
    }
}
__global__ void round_weights_k(const float* __restrict__ wq,
                                const float* __restrict__ wk,
                                const float* __restrict__ wv,
                                const float* __restrict__ wo,
                                float* __restrict__ dst)
{
    const float* src = (blockIdx.y == 0) ? wq : (blockIdx.y == 1) ? wk
                     : (blockIdx.y == 2) ? wv : wo;
    float* d = dst + (size_t)blockIdx.y * DD * DD;
    int idx = (blockIdx.x * 256 + threadIdx.x) << 2;
    if (idx < DD * DD) {
        float4 x = *(const float4*)(src + idx);
        x.x = rndtf(x.x); x.y = rndtf(x.y); x.z = rndtf(x.z); x.w = rndtf(x.w);
        *(float4*)(d + idx) = x;
    }
}

// ============================================================================
// Projection GEMM body: C = ((A[4096,768] @ W[768,768]) + bias) * scale
// A and W are PRE-ROUNDED to tf32 bit patterns. 64m x 128n tile, BK=16,
// 256 thr (2x4 warps, warp 32x32).
// ============================================================================
__device__ __forceinline__
void proj_body(const float* __restrict__ A, const float* __restrict__ W,
               const float* __restrict__ bias, float* __restrict__ C,
               float scale, int rnd_out,
               float As[2][64][20], float Bs[2][16][136])
{
    int t = threadIdx.x, lane = t & 31, w = t >> 5;
    int g = lane >> 2, q = lane & 3;
    int wm = (w & 1) << 5, wn = (w >> 1) << 5;
    int m0 = blockIdx.y << 6, n0 = blockIdx.x << 7;

    {
        int ar = t >> 2, akq = (t & 3) << 2;
        cpa16(&As[0][ar][akq], A + (size_t)(m0 + ar) * DD + akq);
        #pragma unroll
        for (int ch = 0; ch < 2; ch++) {
            int c = t + (ch << 8);
            int br = c >> 5, bnq = (c & 31) << 2;
            cpa16(&Bs[0][br][bnq], W + (size_t)br * DD + n0 + bnq);
        }
    }
    cp_commit();

    float acc[2][4][4] = {};

    for (int it = 0; it < 48; it++) {
        int buf = it & 1;
        if (it < 47) {
            int k0 = (it + 1) << 4;
            int ar = t >> 2, akq = (t & 3) << 2;
            cpa16(&As[buf ^ 1][ar][akq], A + (size_t)(m0 + ar) * DD + k0 + akq);
            #pragma unroll
            for (int ch = 0; ch < 2; ch++) {
                int c = t + (ch << 8);
                int br = c >> 5, bnq = (c & 31) << 2;
                cpa16(&Bs[buf ^ 1][br][bnq], W + (size_t)(k0 + br) * DD + n0 + bnq);
            }
            cp_commit();
            cp_wait<1>();
        } else {
            cp_wait<0>();
        }
        __syncthreads();

        #pragma unroll
        for (int kk = 0; kk < 16; kk += 8) {
            unsigned a[2][4], b2[4][2];
            #pragma unroll
            for (int mi = 0; mi < 2; mi++) {
                const float* pa = &As[buf][wm + (mi << 4) + g][kk + q];
                a[mi][0] = __float_as_uint(pa[0]);
                a[mi][1] = __float_as_uint(pa[8 * 20]);
                a[mi][2] = __float_as_uint(pa[4]);
                a[mi][3] = __float_as_uint(pa[8 * 20 + 4]);
            }
            #pragma unroll
            for (int ni = 0; ni < 4; ni++) {
                const float* pb = &Bs[buf][kk + q][wn + (ni << 3) + g];
                b2[ni][0] = __float_as_uint(pb[0]);
                b2[ni][1] = __float_as_uint(pb[4 * 136]);
            }
            #pragma unroll
            for (int mi = 0; mi < 2; mi++)
                #pragma unroll
                for (int ni = 0; ni < 4; ni++) mma8(acc[mi][ni], a[mi], b2[ni]);
        }
        __syncthreads();
    }

    #pragma unroll
    for (int ni = 0; ni < 4; ni++) {
        int col = n0 + wn + (ni << 3) + (q << 1);
        float b0 = bias[col], b1 = bias[col + 1];
        #pragma unroll
        for (int mi = 0; mi < 2; mi++) {
            int row = m0 + wm + (mi << 4) + g;
            float o0 = (acc[mi][ni][0] + b0) * scale;
            float o1 = (acc[mi][ni][1] + b1) * scale;
            float o2 = (acc[mi][ni][2] + b0) * scale;
            float o3 = (acc[mi][ni][3] + b1) * scale;
            if (rnd_out) { o0 = rndtf(o0); o1 = rndtf(o1); o2 = rndtf(o2); o3 = rndtf(o3); }
            float* c0 = C + (size_t)row * DD + col;
            c0[0] = o0; c0[1] = o1;
            float* c2 = C + (size_t)(row + 8) * DD + col;
            c2[0] = o2; c2[1] = o3;
        }
    }
}

// fused q/k/v projections: blockIdx.z selects which projection
__global__ __launch_bounds__(256, 3)
void projqkv_k(const float* __restrict__ in_r, const float* __restrict__ w_r,
               const float* __restrict__ bq, const float* __restrict__ bk,
               const float* __restrict__ bv,
               float* __restrict__ qo, float* __restrict__ ko, float* __restrict__ vo)
{
    __shared__ float As[2][64][20];
    __shared__ float Bs[2][16][136];
    int z = blockIdx.z;
    const float* A = in_r + (size_t)z * MM * DD;
    const float* W = w_r + (size_t)z * DD * DD;
    const float* bi = (z == 0) ? bq : (z == 1) ? bk : bv;
    float* C = (z == 0) ? qo : (z == 1) ? ko : vo;
    float scale = (z == 0) ? 0.125f : 1.0f;   // fold 1/sqrt(64) into Q
    proj_body(A, W, bi, C, scale, 1, As, Bs);
}

// single projection (output)
__global__ __launch_bounds__(256, 3)
void proj_tf32_k(const float* __restrict__ A, const float* __restrict__ W,
                 const float* __restrict__ bias, float* __restrict__ C,
                 float scale, int rnd_out)
{
    __shared__ float As[2][64][20];
    __shared__ float Bs[2][16][136];
    proj_body(A, W, bias, C, scale, rnd_out, As, Bs);
}

// ============================================================================
// Pass A: g_rz[b,h,j] = 1 / sum_i exp(s),  s = K_j . Q_i  (Q pre-scaled 1/8)
// block = (j-tile 128, bh), 256 thr (2j x 4i warps, warp 64x32).
// K resident, Q i-tiles single-buffered (2 CTAs/SM hide staging latency).
// ============================================================================
__global__ __launch_bounds__(256, 2)
void stats_fused_k(const float* __restrict__ Qp, const float* __restrict__ Kp,
                   float* __restrict__ RZ)
{
    extern __shared__ float sm[];
    float* Kt = sm;                     // [j][d]  stride 68
    float* Qt = sm + 8704;              // [i][d]  stride 68
    float* zp = sm + 2 * 8704;          // [4][128]

    int bh = blockIdx.y;
    int b = bh / HH, h = bh % HH;
    int j0 = blockIdx.x << 7;

    int t = threadIdx.x, lane = t & 31, w = t >> 5;
    int g = lane >> 2, q = lane & 3;
    int wm = (w & 1) << 6, wn = (w >> 1) << 5;   // 2j x 4i warp grid
    int wni = w >> 1;                            // i-column index 0..3

    zp[t] = 0.f; zp[t + 256] = 0.f;

    // K tile resident
    #pragma unroll
    for (int ch = 0; ch < 8; ch++) {
        int c = t + (ch << 8);
        int row = c >> 4, dq = (c & 15) << 2;
        cpa16(&Kt[row * 68 + dq], Kp + (size_t)(b * SS + j0 + row) * DD + h * DKK + dq);
    }
    cp_commit();

    for (int it = 0; it < 16; it++) {
        #pragma unroll
        for (int ch = 0; ch < 8; ch++) {
            int c = t + (ch << 8);
            int row = c >> 4, dq = (c & 15) << 2;
            cpa16(&Qt[row * 68 + dq],
                  Qp + (size_t)(b * SS + (it << 7) + row) * DD + h * DKK + dq);
        }
        cp_commit();
        cp_wait<0>();
        __syncthreads();

        float acc[4][4][4] = {};
        #pragma unroll
        for (int kk = 0; kk < DKK; kk += 8) {
            unsigned a[4][4], b2[4][2];
            #pragma unroll
            for (int mi = 0; mi < 4; mi++) {
                const float* pa = &Kt[(wm + (mi << 4) + g) * 68 + kk + q];
                a[mi][0] = __float_as_uint(pa[0]);
                a[mi][1] = __float_as_uint(pa[8 * 68]);
                a[mi][2] = __float_as_uint(pa[4]);
                a[mi][3] = __float_as_uint(pa[8 * 68 + 4]);
            }
            #pragma unroll
            for (int ni = 0; ni < 4; ni++) {
                const float* pb = &Qt[(wn + (ni << 3) + g) * 68 + kk + q];
                b2[ni][0] = __float_as_uint(pb[0]);
                b2[ni][1] = __float_as_uint(pb[4]);
            }
            #pragma unroll
            for (int mi = 0; mi < 4; mi++)
                #pragma unroll
                for (int ni = 0; ni < 4; ni++) mma8(acc[mi][ni], a[mi], b2[ni]);
        }

        #pragma unroll
        for (int mi = 0; mi < 4; mi++) {
            float s0 = 0.f, s1 = 0.f;
            #pragma unroll
            for (int ni = 0; ni < 4; ni++) {
                s0 += __expf(acc[mi][ni][0]) + __expf(acc[mi][ni][1]);
                s1 += __expf(acc[mi][ni][2]) + __expf(acc[mi][ni][3]);
            }
            s0 += __shfl_xor_sync(0xffffffffu, s0, 1);
            s0 += __shfl_xor_sync(0xffffffffu, s0, 2);
            s1 += __shfl_xor_sync(0xffffffffu, s1, 1);
            s1 += __shfl_xor_sync(0xffffffffu, s1, 2);
            if (q == 0) {
                zp[wni * 128 + wm + (mi << 4) + g]     += s0;
                zp[wni * 128 + wm + (mi << 4) + g + 8] += s1;
            }
        }
        __syncthreads();
    }

    if (t < 128) {
        float z = zp[t] + zp[128 + t] + zp[256 + t] + zp[384 + t];
        RZ[bh * SS + j0 + t] = 1.0f / z;
    }
}

// ============================================================================
// Pass B: O[b,i,h,d] = sum_j exp(s)*rz[j] * V[j,d] (scores recomputed)
// block = (i-tile 128, bh), 512 thr.
// MMA1: 4j x 4i warps (32x32). MMA2: 4i x 4d warps (32i x 16d).
// K and V committed as separate groups; MMA1 waits only for K.
// ============================================================================
__global__ __launch_bounds__(512, 1)
void av_fused_k(const float* __restrict__ Qp, const float* __restrict__ Kp,
                const float* __restrict__ Vp, const float* __restrict__ RZ,
                float* __restrict__ O)
{
    extern __shared__ float smf[];
    float* Qt = smf;                       // [i][d]  stride 68
    float* Kt = smf + 8704;                // [j][d]  stride 68
    float* Vt = smf + 2 * 8704;            // [j][d]  stride 72
    float* Ps = smf + 2 * 8704 + 9216;     // [j][i]  stride 136

    int bh = blockIdx.y;
    int b = bh / HH, h = bh % HH;
    int i0 = blockIdx.x << 7;

    int t = threadIdx.x, lane = t & 31, w = t >> 5;
    int g = lane >> 2, q = lane & 3;
    int wj1 = (w & 3) << 5, wi1 = (w >> 2) << 5;   // MMA1: 4j x 4i
    int wm2 = (w & 3) << 5, wn2 = (w >> 2) << 4;   // MMA2: 4i x 4d (32x16)

    // prologue: Q + K(0) as group0, V(0) as group1
    #pragma unroll
    for (int ch = 0; ch < 4; ch++) {
        int c = t + (ch << 9);
        int row = c >> 4, dq = (c & 15) << 2;
        cpa16(&Qt[row * 68 + dq], Qp + (size_t)(b * SS + i0 + row) * DD + h * DKK + dq);
        cpa16(&Kt[row * 68 + dq], Kp + (size_t)(b * SS + row) * DD + h * DKK + dq);
    }
    cp_commit();
    #pragma unroll
    for (int ch = 0; ch < 4; ch++) {
        int c = t + (ch << 9);
        int row = c >> 4, dq = (c & 15) << 2;
        cpa16(&Vt[row * 72 + dq], Vp + (size_t)(b * SS + row) * DD + h * DKK + dq);
    }
    cp_commit();

    float accO[2][2][4] = {};

    for (int it = 0; it < 16; it++) {
        cp_wait<1>();      // K(it) ready (V(it) may still be in flight)
        __syncthreads();

        float acc1[2][4][4] = {};
        #pragma unroll
        for (int kk = 0; kk < DKK; kk += 8) {
            unsigned a[2][4], b2[4][2];
            #pragma unroll
            for (int mi = 0; mi < 2; mi++) {
                const float* pa = &Kt[(wj1 + (mi << 4) + g) * 68 + kk + q];
                a[mi][0] = __float_as_uint(pa[0]);
                a[mi][1] = __float_as_uint(pa[8 * 68]);
                a[mi][2] = __float_as_uint(pa[4]);
                a[mi][3] = __float_as_uint(pa[8 * 68 + 4]);
            }
            #pragma unroll
            for (int ni = 0; ni < 4; ni++) {
                const float* pb = &Qt[(wi1 + (ni << 3) + g) * 68 + kk + q];
                b2[ni][0] = __float_as_uint(pb[0]);
                b2[ni][1] = __float_as_uint(pb[4]);
            }
            #pragma unroll
            for (int mi = 0; mi < 2; mi++)
                #pragma unroll
                for (int ni = 0; ni < 4; ni++) mma8(acc1[mi][ni], a[mi], b2[ni]);
        }
        __syncthreads();   // Kt reads done

        if (it < 15) {     // prefetch K(it+1)
            #pragma unroll
            for (int ch = 0; ch < 4; ch++) {
                int c = t + (ch << 9);
                int row = c >> 4, dq = (c & 15) << 2;
                cpa16(&Kt[row * 68 + dq],
                      Kp + (size_t)(b * SS + ((it + 1) << 7) + row) * DD + h * DKK + dq);
            }
        }

        #pragma unroll
        for (int mi = 0; mi < 2; mi++) {
            int r0 = wj1 + (mi << 4) + g;
            float rz0 = RZ[bh * SS + (it << 7) + r0];
            float rz1 = RZ[bh * SS + (it << 7) + r0 + 8];
            #pragma unroll
            for (int ni = 0; ni < 4; ni++) {
                int col = wi1 + (ni << 3) + (q << 1);
                float2 p0 = make_float2(rndtf(__expf(acc1[mi][ni][0]) * rz0),
                                        rndtf(__expf(acc1[mi][ni][1]) * rz0));
                float2 p1 = make_float2(rndtf(__expf(acc1[mi][ni][2]) * rz1),
                                        rndtf(__expf(acc1[mi][ni][3]) * rz1));
                *(float2*)&Ps[r0 * 136 + col]       = p0;
                *(float2*)&Ps[(r0 + 8) * 136 + col] = p1;
            }
        }
        cp_wait<0>();      // V(it) ready; also flushes K(it+1) issue into group
        cp_commit();       // close K(it+1) group
        __syncthreads();   // Ps visible + Vt ready

        #pragma unroll
        for (int kk = 0; kk < 128; kk += 8) {
            unsigned a[2][4], b2[2][2];
            #pragma unroll
            for (int mi = 0; mi < 2; mi++) {
                const float* pa = &Ps[(kk + q) * 136 + wm2 + (mi << 4) + g];
                a[mi][0] = __float_as_uint(pa[0]);
                a[mi][1] = __float_as_uint(pa[8]);
                a[mi][2] = __float_as_uint(pa[4 * 136]);
                a[mi][3] = __float_as_uint(pa[4 * 136 + 8]);
            }
            #pragma unroll
            for (int ni = 0; ni < 2; ni++) {
                const float* pb = &Vt[(kk + q) * 72 + wn2 + (ni << 3) + g];
                b2[ni][0] = __float_as_uint(pb[0]);
                b2[ni][1] = __float_as_uint(pb[4 * 72]);
            }
            #pragma unroll
            for (int mi = 0; mi < 2; mi++)
                #pragma unroll
                for (int ni = 0; ni < 2; ni++) mma8(accO[mi][ni], a[mi], b2[ni]);
        }
        __syncthreads();   // Vt reads done

        if (it < 15) {     // prefetch V(it+1)
            #pragma unroll
            for (int ch = 0; ch < 4; ch++) {
                int c = t + (ch << 9);
                int row = c >> 4, dq = (c & 15) << 2;
                cpa16(&Vt[row * 72 + dq],
                      Vp + (size_t)(b * SS + ((it + 1) << 7) + row) * DD + h * DKK + dq);
            }
            cp_commit();
        }
    }

    #pragma unroll
    for (int mi = 0; mi < 2; mi++) {
        #pragma unroll
        for (int ni = 0; ni < 2; ni++) {
            int row = i0 + wm2 + (mi << 4) + g;
            int col = h * DKK + wn2 + (ni << 3) + (q << 1);
            float2 o0 = make_float2(rndtf(accO[mi][ni][0]), rndtf(accO[mi][ni][1]));
            float2 o1 = make_float2(rndtf(accO[mi][ni][2]), rndtf(accO[mi][ni][3]));
            *(float2*)&O[(size_t)(b * SS + row) * DD + col]     = o0;
            *(float2*)&O[(size_t)(b * SS + row + 8) * DD + col] = o1;
        }
    }
}

// ---------------- launch -----------------------------------------------------
extern "C" void kernel_launch(void* const* d_in, const int* in_sizes, int n_in,
                              void* d_out, int out_size)
{
    const float* query = (const float*)d_in[0];
    const float* key   = (const float*)d_in[1];
    const float* value = (const float*)d_in[2];
    const float* Wq = (const float*)d_in[3];
    const float* bq = (const float*)d_in[4];
    const float* Wk = (const float*)d_in[5];
    const float* bk = (const float*)d_in[6];
    const float* Wv = (const float*)d_in[7];
    const float* bv = (const float*)d_in[8];
    const float* Wo = (const float*)d_in[9];
    const float* bo = (const float*)d_in[10];
    float* out = (float*)d_out;

    float *q, *k, *v, *o, *rz, *inr, *wr;
    cudaGetSymbolAddress((void**)&q,   g_q);
    cudaGetSymbolAddress((void**)&k,   g_k);
    cudaGetSymbolAddress((void**)&v,   g_v);
    cudaGetSymbolAddress((void**)&o,   g_o);
    cudaGetSymbolAddress((void**)&rz,  g_rz);
    cudaGetSymbolAddress((void**)&inr, g_in);
    cudaGetSymbolAddress((void**)&wr,  g_w);

    const int SMEM_A = (2 * 8704 + 512) * 4;                      // 71680
    const int SMEM_B = (2 * 8704 + 9216 + 128 * 136) * 4;         // 176128
    cudaFuncSetAttribute(stats_fused_k, cudaFuncAttributeMaxDynamicSharedMemorySize, SMEM_A);
    cudaFuncSetAttribute(av_fused_k,    cudaFuncAttributeMaxDynamicSharedMemorySize, SMEM_B);

    // tf32 pre-rounding prepass
    round_inputs_k <<<dim3((MM * DD / 4 + 255) / 256, 3), 256>>>(query, key, value, inr);
    round_weights_k<<<dim3((DD * DD / 4 + 255) / 256, 4), 256>>>(Wq, Wk, Wv, Wo, wr);

    // fused q/k/v projections: grid (6, 64, 3)
    projqkv_k<<<dim3(DD / 128, MM / 64, 3), 256>>>(inr, wr, bq, bk, bv, q, k, v);

    stats_fused_k<<<dim3(SS / 128, BB * HH), 256, SMEM_A>>>(q, k, rz);

    av_fused_k<<<dim3(SS / 128, BB * HH), 512, SMEM_B>>>(q, k, v, rz, o);

    proj_tf32_k<<<dim3(DD / 128, MM / 64), 256>>>(o, wr + (size_t)3 * DD * DD, bo, out, 1.0f, 0);
}

// round 10
// speedup vs baseline: 1.0106x; 1.0106x over previous
#include <cuda_runtime.h>

#define BB 2
#define SS 2048
#define DD 768
#define HH 12
#define DKK 64
#define MM (BB*SS)   // 4096

// ---------------- scratch (static device globals) ---------------------------
__device__ float g_q[MM * DD];
__device__ float g_k[MM * DD];
__device__ float g_v[MM * DD];
__device__ float g_o[MM * DD];
__device__ float g_rz[BB * HH * SS];   // 1 / sum_i exp(s[b,h,j,i])

// ---------------- helpers ----------------------------------------------------
__device__ __forceinline__ void cpa16(void* s, const void* g) {
    unsigned sa = (unsigned)__cvta_generic_to_shared(s);
    asm volatile("cp.async.ca.shared.global [%0], [%1], 16;\n" :: "r"(sa), "l"(g));
}
__device__ __forceinline__ void cp_commit() { asm volatile("cp.async.commit_group;\n"); }
template<int N> __device__ __forceinline__ void cp_wait() {
    asm volatile("cp.async.wait_group %0;\n" :: "n"(N));
}
__device__ __forceinline__ unsigned f2tf(float f) {
    unsigned u;
    asm("cvt.rna.tf32.f32 %0, %1;" : "=r"(u) : "f"(f));
    return u;
}
__device__ __forceinline__ float rndtf(float f) { return __uint_as_float(f2tf(f)); }

// D += A(16x8) * B(8x8), tf32, f32 accum
__device__ __forceinline__ void mma8(float c[4], const unsigned a[4], const unsigned b[2]) {
    asm volatile(
        "mma.sync.aligned.m16n8k8.row.col.f32.tf32.tf32.f32 "
        "{%0,%1,%2,%3}, {%4,%5,%6,%7}, {%8,%9}, {%0,%1,%2,%3};"
        : "+f"(c[0]), "+f"(c[1]), "+f"(c[2]), "+f"(c[3])
        : "r"(a[0]), "r"(a[1]), "r"(a[2]), "r"(a[3]), "r"(b[0]), "r"(b[1]));
}

// ============================================================================
// Projection GEMM body: C = ((A[4096,768] @ W[768,768]) + bias) * scale
// 64m x 128n tile, BK=32 (24 iters), 256 thr (2x4 warps, warp 32x32).
// Dynamic smem: As[2][64][36] + Bs[2][32][136] = 53248 B -> 3 CTAs/SM.
// ============================================================================
#define PAS(buf,m,k)  As[(buf)*2304 + (m)*36 + (k)]
#define PBS(buf,k,n)  Bs[(buf)*4352 + (k)*136 + (n)]

__device__ __forceinline__
void proj_body(const float* __restrict__ A, const float* __restrict__ W,
               const float* __restrict__ bias, float* __restrict__ C,
               float scale, int rnd_out, float* As, float* Bs)
{
    int t = threadIdx.x, lane = t & 31, w = t >> 5;
    int g = lane >> 2, q = lane & 3;
    int wm = (w & 1) << 5, wn = (w >> 1) << 5;
    int m0 = blockIdx.y << 6, n0 = blockIdx.x << 7;

    {   // stage 0: A 64x32 (2 f4/thr), W 32x128 (4 f4/thr)
        #pragma unroll
        for (int ch = 0; ch < 2; ch++) {
            int c = t + (ch << 8);
            int ar = c >> 3, akq = (c & 7) << 2;
            cpa16(&PAS(0, ar, akq), A + (size_t)(m0 + ar) * DD + akq);
        }
        #pragma unroll
        for (int ch = 0; ch < 4; ch++) {
            int c = t + (ch << 8);
            int br = c >> 5, bnq = (c & 31) << 2;
            cpa16(&PBS(0, br, bnq), W + (size_t)br * DD + n0 + bnq);
        }
    }
    cp_commit();

    float acc[2][4][4] = {};

    for (int it = 0; it < 24; it++) {
        int buf = it & 1;
        if (it < 23) {
            int k0 = (it + 1) << 5;
            #pragma unroll
            for (int ch = 0; ch < 2; ch++) {
                int c = t + (ch << 8);
                int ar = c >> 3, akq = (c & 7) << 2;
                cpa16(&PAS(buf ^ 1, ar, akq), A + (size_t)(m0 + ar) * DD + k0 + akq);
            }
            #pragma unroll
            for (int ch = 0; ch < 4; ch++) {
                int c = t + (ch << 8);
                int br = c >> 5, bnq = (c & 31) << 2;
                cpa16(&PBS(buf ^ 1, br, bnq), W + (size_t)(k0 + br) * DD + n0 + bnq);
            }
            cp_commit();
            cp_wait<1>();
        } else {
            cp_wait<0>();
        }
        __syncthreads();

        #pragma unroll
        for (int kk = 0; kk < 32; kk += 8) {
            unsigned a[2][4], b2[4][2];
            #pragma unroll
            for (int mi = 0; mi < 2; mi++) {
                const float* pa = &PAS(buf, wm + (mi << 4) + g, kk + q);
                a[mi][0] = f2tf(pa[0]);
                a[mi][1] = f2tf(pa[8 * 36]);
                a[mi][2] = f2tf(pa[4]);
                a[mi][3] = f2tf(pa[8 * 36 + 4]);
            }
            #pragma unroll
            for (int ni = 0; ni < 4; ni++) {
                const float* pb = &PBS(buf, kk + q, wn + (ni << 3) + g);
                b2[ni][0] = f2tf(pb[0]);
                b2[ni][1] = f2tf(pb[4 * 136]);
            }
            #pragma unroll
            for (int mi = 0; mi < 2; mi++)
                #pragma unroll
                for (int ni = 0; ni < 4; ni++) mma8(acc[mi][ni], a[mi], b2[ni]);
        }
        __syncthreads();
    }

    #pragma unroll
    for (int ni = 0; ni < 4; ni++) {
        int col = n0 + wn + (ni << 3) + (q << 1);
        float b0 = bias[col], b1 = bias[col + 1];
        #pragma unroll
        for (int mi = 0; mi < 2; mi++) {
            int row = m0 + wm + (mi << 4) + g;
            float o0 = (acc[mi][ni][0] + b0) * scale;
            float o1 = (acc[mi][ni][1] + b1) * scale;
            float o2 = (acc[mi][ni][2] + b0) * scale;
            float o3 = (acc[mi][ni][3] + b1) * scale;
            if (rnd_out) { o0 = rndtf(o0); o1 = rndtf(o1); o2 = rndtf(o2); o3 = rndtf(o3); }
            float* c0 = C + (size_t)row * DD + col;
            c0[0] = o0; c0[1] = o1;
            float* c2 = C + (size_t)(row + 8) * DD + col;
            c2[0] = o2; c2[1] = o3;
        }
    }
}

// fused q/k/v projections: blockIdx.z selects which projection
__global__ __launch_bounds__(256, 3)
void projqkv_k(const float* __restrict__ query, const float* __restrict__ key,
               const float* __restrict__ value,
               const float* __restrict__ Wq, const float* __restrict__ bq,
               const float* __restrict__ Wk, const float* __restrict__ bk,
               const float* __restrict__ Wv, const float* __restrict__ bv,
               float* __restrict__ qo, float* __restrict__ ko, float* __restrict__ vo)
{
    extern __shared__ float smp[];
    float* As = smp;              // 2*64*36 = 4608 floats
    float* Bs = smp + 4608;       // 2*32*136 = 8704 floats
    int z = blockIdx.z;
    const float* A = (z == 0) ? query : (z == 1) ? key : value;
    const float* W = (z == 0) ? Wq : (z == 1) ? Wk : Wv;
    const float* bi = (z == 0) ? bq : (z == 1) ? bk : bv;
    float* C = (z == 0) ? qo : (z == 1) ? ko : vo;
    float scale = (z == 0) ? 0.125f : 1.0f;   // fold 1/sqrt(64) into Q
    proj_body(A, W, bi, C, scale, 1, As, Bs);
}

// single projection (output)
__global__ __launch_bounds__(256, 3)
void proj_tf32_k(const float* __restrict__ A, const float* __restrict__ W,
                 const float* __restrict__ bias, float* __restrict__ C,
                 float scale, int rnd_out)
{
    extern __shared__ float smp[];
    proj_body(A, W, bias, C, scale, rnd_out, smp, smp + 4608);
}

// ============================================================================
// Pass A: g_rz[b,h,j] = 1 / sum_i exp(s),  s = K_j . Q_i  (Q pre-scaled 1/8)
// block = (j-tile 64, bh) -> grid 768 (2.6 waves at 2 CTA/SM, 86% packed).
// 256 thr (2j x 4i warps, warp 32x32). K resident, Q i-tiles streamed.
// smem: Kt[64][68] + Qt[128][68] + zp[4][64] = 53248 B
// ============================================================================
__global__ __launch_bounds__(256, 2)
void stats_fused_k(const float* __restrict__ Qp, const float* __restrict__ Kp,
                   float* __restrict__ RZ)
{
    extern __shared__ float sm[];
    float* Kt = sm;                     // [j][d]  stride 68
    float* Qt = sm + 4352;              // [i][d]  stride 68
    float* zp = sm + 4352 + 8704;       // [4][64]

    int bh = blockIdx.y;
    int b = bh / HH, h = bh % HH;
    int j0 = blockIdx.x << 6;

    int t = threadIdx.x, lane = t & 31, w = t >> 5;
    int g = lane >> 2, q = lane & 3;
    int wm = (w & 1) << 5, wn = (w >> 1) << 5;   // 2j x 4i warp grid (32x32)
    int wni = w >> 1;                            // i-column index 0..3

    zp[t] = 0.f;   // 256 entries

    // K tile resident: 64x64 = 4 f4/thr
    #pragma unroll
    for (int ch = 0; ch < 4; ch++) {
        int c = t + (ch << 8);
        int row = c >> 4, dq = (c & 15) << 2;
        cpa16(&Kt[row * 68 + dq], Kp + (size_t)(b * SS + j0 + row) * DD + h * DKK + dq);
    }
    cp_commit();

    for (int it = 0; it < 16; it++) {
        // stage Q(it): 128x64 = 8 f4/thr (single buffer; 2 CTAs/SM hide latency)
        #pragma unroll
        for (int ch = 0; ch < 8; ch++) {
            int c = t + (ch << 8);
            int row = c >> 4, dq = (c & 15) << 2;
            cpa16(&Qt[row * 68 + dq],
                  Qp + (size_t)(b * SS + (it << 7) + row) * DD + h * DKK + dq);
        }
        cp_commit();
        cp_wait<0>();
        __syncthreads();

        float acc[2][4][4] = {};
        #pragma unroll
        for (int kk = 0; kk < DKK; kk += 8) {
            unsigned a[2][4], b2[4][2];
            #pragma unroll
            for (int mi = 0; mi < 2; mi++) {
                const float* pa = &Kt[(wm + (mi << 4) + g) * 68 + kk + q];
                a[mi][0] = __float_as_uint(pa[0]);
                a[mi][1] = __float_as_uint(pa[8 * 68]);
                a[mi][2] = __float_as_uint(pa[4]);
                a[mi][3] = __float_as_uint(pa[8 * 68 + 4]);
            }
            #pragma unroll
            for (int ni = 0; ni < 4; ni++) {
                const float* pb = &Qt[(wn + (ni << 3) + g) * 68 + kk + q];
                b2[ni][0] = __float_as_uint(pb[0]);
                b2[ni][1] = __float_as_uint(pb[4]);
            }
            #pragma unroll
            for (int mi = 0; mi < 2; mi++)
                #pragma unroll
                for (int ni = 0; ni < 4; ni++) mma8(acc[mi][ni], a[mi], b2[ni]);
        }

        // exp + reduce over i within warp tile, accumulate per-j partials
        #pragma unroll
        for (int mi = 0; mi < 2; mi++) {
            float s0 = 0.f, s1 = 0.f;
            #pragma unroll
            for (int ni = 0; ni < 4; ni++) {
                s0 += __expf(acc[mi][ni][0]) + __expf(acc[mi][ni][1]);
                s1 += __expf(acc[mi][ni][2]) + __expf(acc[mi][ni][3]);
            }
            s0 += __shfl_xor_sync(0xffffffffu, s0, 1);
            s0 += __shfl_xor_sync(0xffffffffu, s0, 2);
            s1 += __shfl_xor_sync(0xffffffffu, s1, 1);
            s1 += __shfl_xor_sync(0xffffffffu, s1, 2);
            if (q == 0) {
                zp[(wni << 6) + wm + (mi << 4) + g]     += s0;
                zp[(wni << 6) + wm + (mi << 4) + g + 8] += s1;
            }
        }
        __syncthreads();   // zp writes + Qt reads done before restage
    }

    if (t < 64) {
        float z = zp[t] + zp[64 + t] + zp[128 + t] + zp[192 + t];
        RZ[bh * SS + j0 + t] = 1.0f / z;
    }
}

// ============================================================================
// Pass B (R8, unchanged): O[b,i,h,d] = sum_j exp(s)*rz[j] * V[j,d]
// block = (i-tile 128, bh), 512 thr.
// MMA1: 4j x 4i warps (32x32). MMA2: 4i x 4d warps (32i x 16d).
// ============================================================================
__global__ __launch_bounds__(512, 1)
void av_fused_k(const float* __restrict__ Qp, const float* __restrict__ Kp,
                const float* __restrict__ Vp, const float* __restrict__ RZ,
                float* __restrict__ O)
{
    extern __shared__ float smf[];
    float* Qt = smf;                       // [i][d]  stride 68
    float* Kt = smf + 8704;                // [j][d]  stride 68
    float* Vt = smf + 2 * 8704;            // [j][d]  stride 72
    float* Ps = smf + 2 * 8704 + 9216;     // [j][i]  stride 136

    int bh = blockIdx.y;
    int b = bh / HH, h = bh % HH;
    int i0 = blockIdx.x << 7;

    int t = threadIdx.x, lane = t & 31, w = t >> 5;
    int g = lane >> 2, q = lane & 3;
    int wj1 = (w & 3) << 5, wi1 = (w >> 2) << 5;   // MMA1: 4j x 4i
    int wm2 = (w & 3) << 5, wn2 = (w >> 2) << 4;   // MMA2: 4i x 4d (32x16)

    #pragma unroll
    for (int ch = 0; ch < 4; ch++) {
        int c = t + (ch << 9);
        int row = c >> 4, dq = (c & 15) << 2;
        cpa16(&Qt[row * 68 + dq], Qp + (size_t)(b * SS + i0 + row) * DD + h * DKK + dq);
        cpa16(&Kt[row * 68 + dq], Kp + (size_t)(b * SS + row) * DD + h * DKK + dq);
    }
    cp_commit();
    #pragma unroll
    for (int ch = 0; ch < 4; ch++) {
        int c = t + (ch << 9);
        int row = c >> 4, dq = (c & 15) << 2;
        cpa16(&Vt[row * 72 + dq], Vp + (size_t)(b * SS + row) * DD + h * DKK + dq);
    }
    cp_commit();

    float accO[2][2][4] = {};

    for (int it = 0; it < 16; it++) {
        cp_wait<1>();      // K(it) ready (V(it) may still be in flight)
        __syncthreads();

        float acc1[2][4][4] = {};
        #pragma unroll
        for (int kk = 0; kk < DKK; kk += 8) {
            unsigned a[2][4], b2[4][2];
            #pragma unroll
            for (int mi = 0; mi < 2; mi++) {
                const float* pa = &Kt[(wj1 + (mi << 4) + g) * 68 + kk + q];
                a[mi][0] = __float_as_uint(pa[0]);
                a[mi][1] = __float_as_uint(pa[8 * 68]);
                a[mi][2] = __float_as_uint(pa[4]);
                a[mi][3] = __float_as_uint(pa[8 * 68 + 4]);
            }
            #pragma unroll
            for (int ni = 0; ni < 4; ni++) {
                const float* pb = &Qt[(wi1 + (ni << 3) + g) * 68 + kk + q];
                b2[ni][0] = __float_as_uint(pb[0]);
                b2[ni][1] = __float_as_uint(pb[4]);
            }
            #pragma unroll
            for (int mi = 0; mi < 2; mi++)
                #pragma unroll
                for (int ni = 0; ni < 4; ni++) mma8(acc1[mi][ni], a[mi], b2[ni]);
        }
        __syncthreads();   // Kt reads done

        if (it < 15) {     // prefetch K(it+1) (uncommitted; flows past V-wait)
            #pragma unroll
            for (int ch = 0; ch < 4; ch++) {
                int c = t + (ch << 9);
                int row = c >> 4, dq = (c & 15) << 2;
                cpa16(&Kt[row * 68 + dq],
                      Kp + (size_t)(b * SS + ((it + 1) << 7) + row) * DD + h * DKK + dq);
            }
        }

        #pragma unroll
        for (int mi = 0; mi < 2; mi++) {
            int r0 = wj1 + (mi << 4) + g;
            float rz0 = RZ[bh * SS + (it << 7) + r0];
            float rz1 = RZ[bh * SS + (it << 7) + r0 + 8];
            #pragma unroll
            for (int ni = 0; ni < 4; ni++) {
                int col = wi1 + (ni << 3) + (q << 1);
                float2 p0 = make_float2(rndtf(__expf(acc1[mi][ni][0]) * rz0),
                                        rndtf(__expf(acc1[mi][ni][1]) * rz0));
                float2 p1 = make_float2(rndtf(__expf(acc1[mi][ni][2]) * rz1),
                                        rndtf(__expf(acc1[mi][ni][3]) * rz1));
                *(float2*)&Ps[r0 * 136 + col]       = p0;
                *(float2*)&Ps[(r0 + 8) * 136 + col] = p1;
            }
        }
        cp_wait<0>();      // V(it) ready (committed groups only)
        cp_commit();       // close K(it+1) group
        __syncthreads();   // Ps visible + Vt ready

        #pragma unroll
        for (int kk = 0; kk < 128; kk += 8) {
            unsigned a[2][4], b2[2][2];
            #pragma unroll
            for (int mi = 0; mi < 2; mi++) {
                const float* pa = &Ps[(kk + q) * 136 + wm2 + (mi << 4) + g];
                a[mi][0] = __float_as_uint(pa[0]);
                a[mi][1] = __float_as_uint(pa[8]);
                a[mi][2] = __float_as_uint(pa[4 * 136]);
                a[mi][3] = __float_as_uint(pa[4 * 136 + 8]);
            }
            #pragma unroll
            for (int ni = 0; ni < 2; ni++) {
                const float* pb = &Vt[(kk + q) * 72 + wn2 + (ni << 3) + g];
                b2[ni][0] = __float_as_uint(pb[0]);
                b2[ni][1] = __float_as_uint(pb[4 * 72]);
            }
            #pragma unroll
            for (int mi = 0; mi < 2; mi++)
                #pragma unroll
                for (int ni = 0; ni < 2; ni++) mma8(accO[mi][ni], a[mi], b2[ni]);
        }
        __syncthreads();   // Vt reads done

        if (it < 15) {     // prefetch V(it+1)
            #pragma unroll
            for (int ch = 0; ch < 4; ch++) {
                int c = t + (ch << 9);
                int row = c >> 4, dq = (c & 15) << 2;
                cpa16(&Vt[row * 72 + dq],
                      Vp + (size_t)(b * SS + ((it + 1) << 7) + row) * DD + h * DKK + dq);
            }
            cp_commit();
        }
    }

    #pragma unroll
    for (int mi = 0; mi < 2; mi++) {
        #pragma unroll
        for (int ni = 0; ni < 2; ni++) {
            int row = i0 + wm2 + (mi << 4) + g;
            int col = h * DKK + wn2 + (ni << 3) + (q << 1);
            float2 o0 = make_float2(rndtf(accO[mi][ni][0]), rndtf(accO[mi][ni][1]));
            float2 o1 = make_float2(rndtf(accO[mi][ni][2]), rndtf(accO[mi][ni][3]));
            *(float2*)&O[(size_t)(b * SS + row) * DD + col]     = o0;
            *(float2*)&O[(size_t)(b * SS + row + 8) * DD + col] = o1;
        }
    }
}

// ---------------- launch -----------------------------------------------------
extern "C" void kernel_launch(void* const* d_in, const int* in_sizes, int n_in,
                              void* d_out, int out_size)
{
    const float* query = (const float*)d_in[0];
    const float* key   = (const float*)d_in[1];
    const float* value = (const float*)d_in[2];
    const float* Wq = (const float*)d_in[3];
    const float* bq = (const float*)d_in[4];
    const float* Wk = (const float*)d_in[5];
    const float* bk = (const float*)d_in[6];
    const float* Wv = (const float*)d_in[7];
    const float* bv = (const float*)d_in[8];
    const float* Wo = (const float*)d_in[9];
    const float* bo = (const float*)d_in[10];
    float* out = (float*)d_out;

    float *q, *k, *v, *o, *rz;
    cudaGetSymbolAddress((void**)&q,  g_q);
    cudaGetSymbolAddress((void**)&k,  g_k);
    cudaGetSymbolAddress((void**)&v,  g_v);
    cudaGetSymbolAddress((void**)&o,  g_o);
    cudaGetSymbolAddress((void**)&rz, g_rz);

    const int SMEM_P = (2 * 64 * 36 + 2 * 32 * 136) * 4;          // 53248
    const int SMEM_A = (64 * 68 + 128 * 68 + 256) * 4;            // 53248
    const int SMEM_B = (2 * 8704 + 9216 + 128 * 136) * 4;         // 176128
    cudaFuncSetAttribute(projqkv_k,     cudaFuncAttributeMaxDynamicSharedMemorySize, SMEM_P);
    cudaFuncSetAttribute(proj_tf32_k,   cudaFuncAttributeMaxDynamicSharedMemorySize, SMEM_P);
    cudaFuncSetAttribute(stats_fused_k, cudaFuncAttributeMaxDynamicSharedMemorySize, SMEM_A);
    cudaFuncSetAttribute(av_fused_k,    cudaFuncAttributeMaxDynamicSharedMemorySize, SMEM_B);

    // fused q/k/v projections: grid (6, 64, 3)
    projqkv_k<<<dim3(DD / 128, MM / 64, 3), 256, SMEM_P>>>(query, key, value,
                                                           Wq, bq, Wk, bk, Wv, bv,
                                                           q, k, v);

    stats_fused_k<<<dim3(SS / 64, BB * HH), 256, SMEM_A>>>(q, k, rz);

    av_fused_k<<<dim3(SS / 128, BB * HH), 512, SMEM_B>>>(q, k, v, rz, o);

    proj_tf32_k<<<dim3(DD / 128, MM / 64), 256, SMEM_P>>>(o, Wo, bo, out, 1.0f, 0);
}

// round 11
// speedup vs baseline: 1.1187x; 1.1070x over previous
#include <cuda_runtime.h>

#define BB 2
#define SS 2048
#define DD 768
#define HH 12
#define DKK 64
#define MM (BB*SS)   // 4096

// ---------------- scratch (static device globals) ---------------------------
__device__ float g_q[MM * DD];
__device__ float g_k[MM * DD];
__device__ float g_v[MM * DD];
__device__ float g_o[MM * DD];
__device__ float g_rz[BB * HH * SS];   // 1 / sum_i exp(s[b,h,j,i])

// ---------------- helpers ----------------------------------------------------
__device__ __forceinline__ void cpa16(void* s, const void* g) {
    unsigned sa = (unsigned)__cvta_generic_to_shared(s);
    asm volatile("cp.async.ca.shared.global [%0], [%1], 16;\n" :: "r"(sa), "l"(g));
}
__device__ __forceinline__ void cp_commit() { asm volatile("cp.async.commit_group;\n"); }
template<int N> __device__ __forceinline__ void cp_wait() {
    asm volatile("cp.async.wait_group %0;\n" :: "n"(N));
}
__device__ __forceinline__ unsigned f2tf(float f) {
    unsigned u;
    asm("cvt.rna.tf32.f32 %0, %1;" : "=r"(u) : "f"(f));
    return u;
}
__device__ __forceinline__ float rndtf(float f) { return __uint_as_float(f2tf(f)); }

// D += A(16x8) * B(8x8), tf32, f32 accum
__device__ __forceinline__ void mma8(float c[4], const unsigned a[4], const unsigned b[2]) {
    asm volatile(
        "mma.sync.aligned.m16n8k8.row.col.f32.tf32.tf32.f32 "
        "{%0,%1,%2,%3}, {%4,%5,%6,%7}, {%8,%9}, {%0,%1,%2,%3};"
        : "+f"(c[0]), "+f"(c[1]), "+f"(c[2]), "+f"(c[3])
        : "r"(a[0]), "r"(a[1]), "r"(a[2]), "r"(a[3]), "r"(b[0]), "r"(b[1]));
}

// ============================================================================
// Projection GEMM body (R10, kept): C = ((A @ W) + bias) * scale
// 64m x 128n tile, BK=32 (24 iters), 256 thr (2x4 warps, warp 32x32).
// Dynamic smem: As[2][64][36] + Bs[2][32][136] = 53248 B -> 3 CTAs/SM.
// ============================================================================
#define PAS(buf,m,k)  As[(buf)*2304 + (m)*36 + (k)]
#define PBS(buf,k,n)  Bs[(buf)*4352 + (k)*136 + (n)]

__device__ __forceinline__
void proj_body(const float* __restrict__ A, const float* __restrict__ W,
               const float* __restrict__ bias, float* __restrict__ C,
               float scale, int rnd_out, float* As, float* Bs)
{
    int t = threadIdx.x, lane = t & 31, w = t >> 5;
    int g = lane >> 2, q = lane & 3;
    int wm = (w & 1) << 5, wn = (w >> 1) << 5;
    int m0 = blockIdx.y << 6, n0 = blockIdx.x << 7;

    {
        #pragma unroll
        for (int ch = 0; ch < 2; ch++) {
            int c = t + (ch << 8);
            int ar = c >> 3, akq = (c & 7) << 2;
            cpa16(&PAS(0, ar, akq), A + (size_t)(m0 + ar) * DD + akq);
        }
        #pragma unroll
        for (int ch = 0; ch < 4; ch++) {
            int c = t + (ch << 8);
            int br = c >> 5, bnq = (c & 31) << 2;
            cpa16(&PBS(0, br, bnq), W + (size_t)br * DD + n0 + bnq);
        }
    }
    cp_commit();

    float acc[2][4][4] = {};

    for (int it = 0; it < 24; it++) {
        int buf = it & 1;
        if (it < 23) {
            int k0 = (it + 1) << 5;
            #pragma unroll
            for (int ch = 0; ch < 2; ch++) {
                int c = t + (ch << 8);
                int ar = c >> 3, akq = (c & 7) << 2;
                cpa16(&PAS(buf ^ 1, ar, akq), A + (size_t)(m0 + ar) * DD + k0 + akq);
            }
            #pragma unroll
            for (int ch = 0; ch < 4; ch++) {
                int c = t + (ch << 8);
                int br = c >> 5, bnq = (c & 31) << 2;
                cpa16(&PBS(buf ^ 1, br, bnq), W + (size_t)(k0 + br) * DD + n0 + bnq);
            }
            cp_commit();
            cp_wait<1>();
        } else {
            cp_wait<0>();
        }
        __syncthreads();

        #pragma unroll
        for (int kk = 0; kk < 32; kk += 8) {
            unsigned a[2][4], b2[4][2];
            #pragma unroll
            for (int mi = 0; mi < 2; mi++) {
                const float* pa = &PAS(buf, wm + (mi << 4) + g, kk + q);
                a[mi][0] = f2tf(pa[0]);
                a[mi][1] = f2tf(pa[8 * 36]);
                a[mi][2] = f2tf(pa[4]);
                a[mi][3] = f2tf(pa[8 * 36 + 4]);
            }
            #pragma unroll
            for (int ni = 0; ni < 4; ni++) {
                const float* pb = &PBS(buf, kk + q, wn + (ni << 3) + g);
                b2[ni][0] = f2tf(pb[0]);
                b2[ni][1] = f2tf(pb[4 * 136]);
            }
            #pragma unroll
            for (int mi = 0; mi < 2; mi++)
                #pragma unroll
                for (int ni = 0; ni < 4; ni++) mma8(acc[mi][ni], a[mi], b2[ni]);
        }
        __syncthreads();
    }

    #pragma unroll
    for (int ni = 0; ni < 4; ni++) {
        int col = n0 + wn + (ni << 3) + (q << 1);
        float b0 = bias[col], b1 = bias[col + 1];
        #pragma unroll
        for (int mi = 0; mi < 2; mi++) {
            int row = m0 + wm + (mi << 4) + g;
            float o0 = (acc[mi][ni][0] + b0) * scale;
            float o1 = (acc[mi][ni][1] + b1) * scale;
            float o2 = (acc[mi][ni][2] + b0) * scale;
            float o3 = (acc[mi][ni][3] + b1) * scale;
            if (rnd_out) { o0 = rndtf(o0); o1 = rndtf(o1); o2 = rndtf(o2); o3 = rndtf(o3); }
            float* c0 = C + (size_t)row * DD + col;
            c0[0] = o0; c0[1] = o1;
            float* c2 = C + (size_t)(row + 8) * DD + col;
            c2[0] = o2; c2[1] = o3;
        }
    }
}

__global__ __launch_bounds__(256, 3)
void projqkv_k(const float* __restrict__ query, const float* __restrict__ key,
               const float* __restrict__ value,
               const float* __restrict__ Wq, const float* __restrict__ bq,
               const float* __restrict__ Wk, const float* __restrict__ bk,
               const float* __restrict__ Wv, const float* __restrict__ bv,
               float* __restrict__ qo, float* __restrict__ ko, float* __restrict__ vo)
{
    extern __shared__ float smp[];
    float* As = smp;
    float* Bs = smp + 4608;
    int z = blockIdx.z;
    const float* A = (z == 0) ? query : (z == 1) ? key : value;
    const float* W = (z == 0) ? Wq : (z == 1) ? Wk : Wv;
    const float* bi = (z == 0) ? bq : (z == 1) ? bk : bv;
    float* C = (z == 0) ? qo : (z == 1) ? ko : vo;
    float scale = (z == 0) ? 0.125f : 1.0f;
    proj_body(A, W, bi, C, scale, 1, As, Bs);
}

__global__ __launch_bounds__(256, 3)
void proj_tf32_k(const float* __restrict__ A, const float* __restrict__ W,
                 const float* __restrict__ bias, float* __restrict__ C,
                 float scale, int rnd_out)
{
    extern __shared__ float smp[];
    proj_body(A, W, bias, C, scale, rnd_out, smp, smp + 4608);
}

// ============================================================================
// Pass A (R8 config, best measured): g_rz = 1 / sum_i exp(s)
// block = (j-tile 128, bh) grid 384, 256 thr (2j x 4i warps, warp 64x32).
// K resident, Q i-tiles single-buffered. smem 71680 B -> 2 CTAs/SM.
// ============================================================================
__global__ __launch_bounds__(256, 2)
void stats_fused_k(const float* __restrict__ Qp, const float* __restrict__ Kp,
                   float* __restrict__ RZ)
{
    extern __shared__ float sm[];
    float* Kt = sm;                     // [j][d]  stride 68
    float* Qt = sm + 8704;              // [i][d]  stride 68
    float* zp = sm + 2 * 8704;          // [4][128]

    int bh = blockIdx.y;
    int b = bh / HH, h = bh % HH;
    int j0 = blockIdx.x << 7;

    int t = threadIdx.x, lane = t & 31, w = t >> 5;
    int g = lane >> 2, q = lane & 3;
    int wm = (w & 1) << 6, wn = (w >> 1) << 5;
    int wni = w >> 1;

    zp[t] = 0.f; zp[t + 256] = 0.f;

    #pragma unroll
    for (int ch = 0; ch < 8; ch++) {
        int c = t + (ch << 8);
        int row = c >> 4, dq = (c & 15) << 2;
        cpa16(&Kt[row * 68 + dq], Kp + (size_t)(b * SS + j0 + row) * DD + h * DKK + dq);
    }
    cp_commit();

    for (int it = 0; it < 16; it++) {
        #pragma unroll
        for (int ch = 0; ch < 8; ch++) {
            int c = t + (ch << 8);
            int row = c >> 4, dq = (c & 15) << 2;
            cpa16(&Qt[row * 68 + dq],
                  Qp + (size_t)(b * SS + (it << 7) + row) * DD + h * DKK + dq);
        }
        cp_commit();
        cp_wait<0>();
        __syncthreads();

        float acc[4][4][4] = {};
        #pragma unroll
        for (int kk = 0; kk < DKK; kk += 8) {
            unsigned a[4][4], b2[4][2];
            #pragma unroll
            for (int mi = 0; mi < 4; mi++) {
                const float* pa = &Kt[(wm + (mi << 4) + g) * 68 + kk + q];
                a[mi][0] = __float_as_uint(pa[0]);
                a[mi][1] = __float_as_uint(pa[8 * 68]);
                a[mi][2] = __float_as_uint(pa[4]);
                a[mi][3] = __float_as_uint(pa[8 * 68 + 4]);
            }
            #pragma unroll
            for (int ni = 0; ni < 4; ni++) {
                const float* pb = &Qt[(wn + (ni << 3) + g) * 68 + kk + q];
                b2[ni][0] = __float_as_uint(pb[0]);
                b2[ni][1] = __float_as_uint(pb[4]);
            }
            #pragma unroll
            for (int mi = 0; mi < 4; mi++)
                #pragma unroll
                for (int ni = 0; ni < 4; ni++) mma8(acc[mi][ni], a[mi], b2[ni]);
        }

        #pragma unroll
        for (int mi = 0; mi < 4; mi++) {
            float s0 = 0.f, s1 = 0.f;
            #pragma unroll
            for (int ni = 0; ni < 4; ni++) {
                s0 += __expf(acc[mi][ni][0]) + __expf(acc[mi][ni][1]);
                s1 += __expf(acc[mi][ni][2]) + __expf(acc[mi][ni][3]);
            }
            s0 += __shfl_xor_sync(0xffffffffu, s0, 1);
            s0 += __shfl_xor_sync(0xffffffffu, s0, 2);
            s1 += __shfl_xor_sync(0xffffffffu, s1, 1);
            s1 += __shfl_xor_sync(0xffffffffu, s1, 2);
            if (q == 0) {
                zp[wni * 128 + wm + (mi << 4) + g]     += s0;
                zp[wni * 128 + wm + (mi << 4) + g + 8] += s1;
            }
        }
        __syncthreads();
    }

    if (t < 128) {
        float z = zp[t] + zp[128 + t] + zp[256 + t] + zp[384 + t];
        RZ[bh * SS + j0 + t] = 1.0f / z;
    }
}

// ============================================================================
// Pass B: O[b,i,h,d] = sum_j exp(s)*rz[j] * V[j,d]  (scores recomputed)
// RETILED: block = (i-tile 128, bh), 256 thr, j-loop tile 64 (32 iters).
// MMA1: 2j x 4i warps (32x32). MMA2: 4i x 2d warps (32x32).
// smem: Qt[128][68] + Kt[64][68] + Vt[64][72] + Ps[64][136] = 105472 B
//   -> 2 CTAs/SM: phases of the two CTAs interleave, hiding exp/store.
// ============================================================================
__global__ __launch_bounds__(256, 2)
void av_fused_k(const float* __restrict__ Qp, const float* __restrict__ Kp,
                const float* __restrict__ Vp, const float* __restrict__ RZ,
                float* __restrict__ O)
{
    extern __shared__ float smf[];
    float* Qt = smf;                       // [i][d]  stride 68 (8704 floats)
    float* Kt = smf + 8704;                // [j][d]  stride 68 (4352)
    float* Vt = smf + 8704 + 4352;         // [j][d]  stride 72 (4608)
    float* Ps = smf + 8704 + 4352 + 4608;  // [j][i]  stride 136 (8704)

    int bh = blockIdx.y;
    int b = bh / HH, h = bh % HH;
    int i0 = blockIdx.x << 7;

    int t = threadIdx.x, lane = t & 31, w = t >> 5;
    int g = lane >> 2, q = lane & 3;
    int wj1 = (w & 1) << 5, wi1 = (w >> 1) << 5;   // MMA1: 2j x 4i (32x32)
    int wm2 = (w & 3) << 5, wn2 = (w >> 2) << 5;   // MMA2: 4i x 2d (32x32)

    // prologue: Q resident (8 f4/thr) + K(0) (4 f4/thr) group0; V(0) group1
    #pragma unroll
    for (int ch = 0; ch < 8; ch++) {
        int c = t + (ch << 8);
        int row = c >> 4, dq = (c & 15) << 2;
        cpa16(&Qt[row * 68 + dq], Qp + (size_t)(b * SS + i0 + row) * DD + h * DKK + dq);
    }
    #pragma unroll
    for (int ch = 0; ch < 4; ch++) {
        int c = t + (ch << 8);
        int row = c >> 4, dq = (c & 15) << 2;
        cpa16(&Kt[row * 68 + dq], Kp + (size_t)(b * SS + row) * DD + h * DKK + dq);
    }
    cp_commit();
    #pragma unroll
    for (int ch = 0; ch < 4; ch++) {
        int c = t + (ch << 8);
        int row = c >> 4, dq = (c & 15) << 2;
        cpa16(&Vt[row * 72 + dq], Vp + (size_t)(b * SS + row) * DD + h * DKK + dq);
    }
    cp_commit();

    float accO[2][4][4] = {};

    for (int it = 0; it < 32; it++) {
        int jc = it << 6;
        cp_wait<1>();      // K(it) ready (V(it) may still be in flight)
        __syncthreads();

        // ---- MMA1: S = K_tile(64j) @ Q_tile(128i)^T over d=64 ----
        float acc1[2][4][4] = {};
        #pragma unroll
        for (int kk = 0; kk < DKK; kk += 8) {
            unsigned a[2][4], b2[4][2];
            #pragma unroll
            for (int mi = 0; mi < 2; mi++) {
                const float* pa = &Kt[(wj1 + (mi << 4) + g) * 68 + kk + q];
                a[mi][0] = __float_as_uint(pa[0]);
                a[mi][1] = __float_as_uint(pa[8 * 68]);
                a[mi][2] = __float_as_uint(pa[4]);
                a[mi][3] = __float_as_uint(pa[8 * 68 + 4]);
            }
            #pragma unroll
            for (int ni = 0; ni < 4; ni++) {
                const float* pb = &Qt[(wi1 + (ni << 3) + g) * 68 + kk + q];
                b2[ni][0] = __float_as_uint(pb[0]);
                b2[ni][1] = __float_as_uint(pb[4]);
            }
            #pragma unroll
            for (int mi = 0; mi < 2; mi++)
                #pragma unroll
                for (int ni = 0; ni < 4; ni++) mma8(acc1[mi][ni], a[mi], b2[ni]);
        }
        __syncthreads();   // Kt reads done

        if (it < 31) {     // prefetch K(it+1) (uncommitted yet)
            #pragma unroll
            for (int ch = 0; ch < 4; ch++) {
                int c = t + (ch << 8);
                int row = c >> 4, dq = (c & 15) << 2;
                cpa16(&Kt[row * 68 + dq],
                      Kp + (size_t)(b * SS + jc + 64 + row) * DD + h * DKK + dq);
            }
        }

        // ---- P = round_tf32( exp(s) * rz[j] ) -> Ps[j][i] ----
        #pragma unroll
        for (int mi = 0; mi < 2; mi++) {
            int r0 = wj1 + (mi << 4) + g;
            float rz0 = RZ[bh * SS + jc + r0];
            float rz1 = RZ[bh * SS + jc + r0 + 8];
            #pragma unroll
            for (int ni = 0; ni < 4; ni++) {
                int col = wi1 + (ni << 3) + (q << 1);
                float2 p0 = make_float2(rndtf(__expf(acc1[mi][ni][0]) * rz0),
                                        rndtf(__expf(acc1[mi][ni][1]) * rz0));
                float2 p1 = make_float2(rndtf(__expf(acc1[mi][ni][2]) * rz1),
                                        rndtf(__expf(acc1[mi][ni][3]) * rz1));
                *(float2*)&Ps[r0 * 136 + col]       = p0;
                *(float2*)&Ps[(r0 + 8) * 136 + col] = p1;
            }
        }
        cp_wait<0>();      // V(it) ready (committed groups only)
        cp_commit();       // close K(it+1) group
        __syncthreads();   // Ps visible + Vt ready

        // ---- MMA2: O += P^T(128i x 64j) @ V(64j x 64d) ----
        #pragma unroll
        for (int kk = 0; kk < 64; kk += 8) {
            unsigned a[2][4], b2[4][2];
            #pragma unroll
            for (int mi = 0; mi < 2; mi++) {
                const float* pa = &Ps[(kk + q) * 136 + wm2 + (mi << 4) + g];
                a[mi][0] = __float_as_uint(pa[0]);
                a[mi][1] = __float_as_uint(pa[8]);
                a[mi][2] = __float_as_uint(pa[4 * 136]);
                a[mi][3] = __float_as_uint(pa[4 * 136 + 8]);
            }
            #pragma unroll
            for (int ni = 0; ni < 4; ni++) {
                const float* pb = &Vt[(kk + q) * 72 + wn2 + (ni << 3) + g];
                b2[ni][0] = __float_as_uint(pb[0]);
                b2[ni][1] = __float_as_uint(pb[4 * 72]);
            }
            #pragma unroll
            for (int mi = 0; mi < 2; mi++)
                #pragma unroll
                for (int ni = 0; ni < 4; ni++) mma8(accO[mi][ni], a[mi], b2[ni]);
        }
        __syncthreads();   // Vt reads done

        if (it < 31) {     // prefetch V(it+1)
            #pragma unroll
            for (int ch = 0; ch < 4; ch++) {
                int c = t + (ch << 8);
                int row = c >> 4, dq = (c & 15) << 2;
                cpa16(&Vt[row * 72 + dq],
                      Vp + (size_t)(b * SS + jc + 64 + row) * DD + h * DKK + dq);
            }
            cp_commit();
        }
    }

    // epilogue: O rounded to tf32 (consumed by final projection)
    #pragma unroll
    for (int mi = 0; mi < 2; mi++) {
        #pragma unroll
        for (int ni = 0; ni < 4; ni++) {
            int row = i0 + wm2 + (mi << 4) + g;
            int col = h * DKK + wn2 + (ni << 3) + (q << 1);
            float2 o0 = make_float2(rndtf(accO[mi][ni][0]), rndtf(accO[mi][ni][1]));
            float2 o1 = make_float2(rndtf(accO[mi][ni][2]), rndtf(accO[mi][ni][3]));
            *(float2*)&O[(size_t)(b * SS + row) * DD + col]     = o0;
            *(float2*)&O[(size_t)(b * SS + row + 8) * DD + col] = o1;
        }
    }
}

// ---------------- launch -----------------------------------------------------
extern "C" void kernel_launch(void* const* d_in, const int* in_sizes, int n_in,
                              void* d_out, int out_size)
{
    const float* query = (const float*)d_in[0];
    const float* key   = (const float*)d_in[1];
    const float* value = (const float*)d_in[2];
    const float* Wq = (const float*)d_in[3];
    const float* bq = (const float*)d_in[4];
    const float* Wk = (const float*)d_in[5];
    const float* bk = (const float*)d_in[6];
    const float* Wv = (const float*)d_in[7];
    const float* bv = (const float*)d_in[8];
    const float* Wo = (const float*)d_in[9];
    const float* bo = (const float*)d_in[10];
    float* out = (float*)d_out;

    float *q, *k, *v, *o, *rz;
    cudaGetSymbolAddress((void**)&q,  g_q);
    cudaGetSymbolAddress((void**)&k,  g_k);
    cudaGetSymbolAddress((void**)&v,  g_v);
    cudaGetSymbolAddress((void**)&o,  g_o);
    cudaGetSymbolAddress((void**)&rz, g_rz);

    const int SMEM_P = (2 * 64 * 36 + 2 * 32 * 136) * 4;          // 53248
    const int SMEM_A = (2 * 8704 + 512) * 4;                      // 71680
    const int SMEM_B = (8704 + 4352 + 4608 + 8704) * 4;           // 105472
    cudaFuncSetAttribute(projqkv_k,     cudaFuncAttributeMaxDynamicSharedMemorySize, SMEM_P);
    cudaFuncSetAttribute(proj_tf32_k,   cudaFuncAttributeMaxDynamicSharedMemorySize, SMEM_P);
    cudaFuncSetAttribute(stats_fused_k, cudaFuncAttributeMaxDynamicSharedMemorySize, SMEM_A);
    cudaFuncSetAttribute(av_fused_k,    cudaFuncAttributeMaxDynamicSharedMemorySize, SMEM_B);

    // fused q/k/v projections: grid (6, 64, 3)
    projqkv_k<<<dim3(DD / 128, MM / 64, 3), 256, SMEM_P>>>(query, key, value,
                                                           Wq, bq, Wk, bk, Wv, bv,
                                                           q, k, v);

    stats_fused_k<<<dim3(SS / 128, BB * HH), 256, SMEM_A>>>(q, k, rz);

    av_fused_k<<<dim3(SS / 128, BB * HH), 256, SMEM_B>>>(q, k, v, rz, o);

    proj_tf32_k<<<dim3(DD / 128, MM / 64), 256, SMEM_P>>>(o, Wo, bo, out, 1.0f, 0);
}